// round 3
// baseline (speedup 1.0000x reference)
#include <cuda_runtime.h>
#include <math.h>

#define H 1024
#define L 4096
#define G3 3072
#define NCTA 64     // CTAs per direction in recurrence
#define UNITS 16    // hidden units per CTA (16 warps, 1 unit/warp)
#define ARRIVALS (NCTA * UNITS)   // per-warp arrivals per step

typedef unsigned long long u64;

// Scratch: precomputed input projections gi = Wih @ x_t + bih, per direction.
__device__ float g_Gi[2][L][G3];            // ~100.7 MB
__device__ unsigned int g_ctr[2 * L];       // per-step arrival counters
__device__ float g_h[2][2][H];              // [dir][step parity][H] h exchange

// ---------------------------------------------------------------------------
// PTX helpers
// ---------------------------------------------------------------------------
__device__ __forceinline__ void ffma2(u64& acc, u64 a, u64 b) {
    asm("fma.rn.f32x2 %0, %1, %2, %3;" : "=l"(acc) : "l"(a), "l"(b), "l"(acc));
}
__device__ __forceinline__ float hsum2(u64 v) {
    float lo, hi;
    asm("mov.b64 {%0, %1}, %2;" : "=f"(lo), "=f"(hi) : "l"(v));
    return lo + hi;
}
__device__ __forceinline__ u64 dup2(float v) {
    u64 r;
    asm("mov.b64 %0, {%1, %1};" : "=l"(r) : "f"(v));
    return r;
}
__device__ __forceinline__ void arrive_release(unsigned int* p) {
    asm volatile("red.release.gpu.global.add.u32 [%0], 1;" :: "l"(p) : "memory");
}
__device__ __forceinline__ unsigned int ld_acquire(const unsigned int* p) {
    unsigned int v;
    asm volatile("ld.acquire.gpu.global.u32 %0, [%1];" : "=r"(v) : "l"(p) : "memory");
    return v;
}

// ---------------------------------------------------------------------------
// Reset counters
// ---------------------------------------------------------------------------
__global__ void reset_kernel() {
    int i = blockIdx.x * blockDim.x + threadIdx.x;
    for (int k = i; k < 2 * L; k += gridDim.x * blockDim.x) g_ctr[k] = 0u;
}

// ---------------------------------------------------------------------------
// Phase 1: Gi[d][t][n] = sum_k x[t][k] * W[n][k] + b[n]
// SGEMM-NT with f32x2 packed FMAs: m-rows paired into f32x2 accumulators.
// B tile stored duplicated ({b,b} u64) with bank-conflict-free padded layout.
// ---------------------------------------------------------------------------
__device__ __forceinline__ int bpad(int n) { return n + (n >> 2); }  // pad 1 u64 per 4

__global__ __launch_bounds__(256) void gi_gemm(
    const float* __restrict__ x,
    const float* __restrict__ Wf, const float* __restrict__ bf,
    const float* __restrict__ Wr, const float* __restrict__ br)
{
    const int d  = blockIdx.z;
    const float* __restrict__ W = d ? Wr : Wf;
    const float* __restrict__ b = d ? br : bf;
    const int m0 = blockIdx.y * 128;
    const int n0 = blockIdx.x * 64;

    __shared__ float As[16][132];          // [k][m]
    __shared__ u64   Bsd[16][80];          // [k][padded n], value duplicated {b,b}

    const int tid = threadIdx.x;
    const int tx  = tid & 15;              // n: 16 groups * 4 cols
    const int ty  = tid >> 4;              // m: 16 groups * 8 rows (4 f32x2 pairs)

    u64 acc[4][4];                         // [m-pair][n]
    #pragma unroll
    for (int i = 0; i < 4; ++i)
        #pragma unroll
        for (int j = 0; j < 4; ++j) acc[i][j] = 0ull;

    for (int k0 = 0; k0 < H; k0 += 16) {
        // A tile: 128 rows x 16 k
        #pragma unroll
        for (int it = 0; it < 2; ++it) {
            int idx = tid + it * 256;
            int row = idx >> 2, kq = idx & 3;
            float4 v = *(const float4*)(x + (size_t)(m0 + row) * H + k0 + kq * 4);
            As[kq * 4 + 0][row] = v.x;
            As[kq * 4 + 1][row] = v.y;
            As[kq * 4 + 2][row] = v.z;
            As[kq * 4 + 3][row] = v.w;
        }
        // B tile: 64 rows x 16 k, duplicated into u64 pairs
        {
            int row = tid >> 2, kq = tid & 3;
            float4 v = *(const float4*)(W + (size_t)(n0 + row) * H + k0 + kq * 4);
            int p = bpad(row);
            Bsd[kq * 4 + 0][p] = dup2(v.x);
            Bsd[kq * 4 + 1][p] = dup2(v.y);
            Bsd[kq * 4 + 2][p] = dup2(v.z);
            Bsd[kq * 4 + 3][p] = dup2(v.w);
        }
        __syncthreads();

        #pragma unroll
        for (int kk = 0; kk < 16; ++kk) {
            ulonglong2 A0 = *(const ulonglong2*)&As[kk][ty * 8];
            ulonglong2 A1 = *(const ulonglong2*)&As[kk][ty * 8 + 4];
            u64 am[4] = {A0.x, A0.y, A1.x, A1.y};
            const u64* brow = &Bsd[kk][bpad(tx * 4)];
            u64 bv[4] = {brow[0], brow[1], brow[2], brow[3]};
            #pragma unroll
            for (int i = 0; i < 4; ++i)
                #pragma unroll
                for (int j = 0; j < 4; ++j)
                    ffma2(acc[i][j], am[i], bv[j]);
        }
        __syncthreads();
    }

    // Epilogue: unpack m-pairs, add bias, store
    float* __restrict__ C = &g_Gi[d][0][0];
    float4 bias = *(const float4*)(b + n0 + tx * 4);
    float bias_a[4] = {bias.x, bias.y, bias.z, bias.w};
    #pragma unroll
    for (int p = 0; p < 4; ++p) {
        float lo[4], hi[4];
        #pragma unroll
        for (int j = 0; j < 4; ++j) {
            asm("mov.b64 {%0, %1}, %2;" : "=f"(lo[j]), "=f"(hi[j]) : "l"(acc[p][j]));
            lo[j] += bias_a[j];
            hi[j] += bias_a[j];
        }
        int m = m0 + ty * 8 + 2 * p;
        *(float4*)(C + (size_t)m * G3 + n0 + tx * 4)       = make_float4(lo[0], lo[1], lo[2], lo[3]);
        *(float4*)(C + (size_t)(m + 1) * G3 + n0 + tx * 4) = make_float4(hi[0], hi[1], hi[2], hi[3]);
    }
}

// ---------------------------------------------------------------------------
// Phase 2: persistent register-resident GRU recurrence.
// Warp-autonomous sync: each warp polls, loads its 1/16 h slice, ONE
// __syncthreads, computes, stores its unit's h, per-warp release-arrive.
// SMEM h double-buffered by step parity.
// ---------------------------------------------------------------------------
__device__ __forceinline__ float sigm(float v) {
    return 1.0f / (1.0f + __expf(-v));
}
__device__ __forceinline__ float tanh_fast(float v) {
    return 2.0f / (1.0f + __expf(-2.0f * v)) - 1.0f;
}

__global__ __launch_bounds__(512, 1) void gru_recur(
    const float* __restrict__ Whh_f, const float* __restrict__ bhh_f,
    const float* __restrict__ Whh_r, const float* __restrict__ bhh_r,
    float* __restrict__ out)
{
    const int bx  = blockIdx.x;
    const int d   = (bx >= NCTA) ? 1 : 0;
    const int cta = d ? bx - NCTA : bx;
    const int u0  = cta * UNITS;
    const int tid = threadIdx.x;
    const int w   = tid >> 5;
    const int l   = tid & 31;
    const int u   = u0 + w;

    const float* __restrict__ Whh = d ? Whh_r : Whh_f;
    const float* __restrict__ bhh = d ? bhh_r : bhh_f;
    const float* __restrict__ Gi  = &g_Gi[d][0][0];
    unsigned int* ctr = g_ctr + d * L;
    float* hbuf0 = &g_h[d][0][0];
    float* hbuf1 = &g_h[d][1][0];

    __shared__ float h_s[2][H];            // double-buffered by step parity

    // Register-resident weights: lane l holds floats [128c + 4l .. +3], c=0..7.
    u64 w0[16], w1[16], w2[16];
    {
        const u64* r0 = (const u64*)(Whh + (size_t)(u         ) * H + 4 * l);
        const u64* r1 = (const u64*)(Whh + (size_t)(u + H     ) * H + 4 * l);
        const u64* r2 = (const u64*)(Whh + (size_t)(u + 2 * H ) * H + 4 * l);
        #pragma unroll
        for (int c = 0; c < 8; ++c) {
            w0[2*c] = r0[c*64]; w0[2*c+1] = r0[c*64+1];
            w1[2*c] = r1[c*64]; w1[2*c+1] = r1[c*64+1];
            w2[2*c] = r2[c*64]; w2[2*c+1] = r2[c*64+1];
        }
    }
    const float b_r = bhh[u];
    const float b_z = bhh[u + H];
    const float b_n = bhh[u + 2 * H];

    for (int s = 0; s < L; ++s) {
        const int t = d ? (L - 1 - s) : s;
        const int p = s & 1;

        // Gi prefetch (independent of the h dependency).
        float gi_r = 0.f, gi_z = 0.f, gi_n = 0.f;
        if (l == 0) {
            const float* g = Gi + (size_t)t * G3;
            gi_r = __ldg(g + u);
            gi_z = __ldg(g + u + H);
            gi_n = __ldg(g + u + 2 * H);
        }

        // Warp-autonomous: poll previous step done, load this warp's h slice.
        if (s == 0) {
            ((float2*)h_s[0])[w * 32 + l] = make_float2(0.f, 0.f);
        } else {
            if (l == 0) {
                while (ld_acquire(&ctr[s - 1]) < (unsigned)ARRIVALS) { }
            }
            __syncwarp();
            const float* src = ((s - 1) & 1) ? hbuf1 : hbuf0;
            float2 v = __ldcg((const float2*)(src + w * 64) + l);
            ((float2*)h_s[p])[w * 32 + l] = v;
        }
        __syncthreads();   // the only CTA-wide barrier per step

        // Dot products: 3 rows x 1024, packed f32x2.
        const u64* hs64 = (const u64*)h_s[p];
        u64 a0 = 0ull, a1 = 0ull, a2 = 0ull;
        #pragma unroll
        for (int c = 0; c < 8; ++c) {
            u64 h0 = hs64[c * 64 + 2 * l];
            u64 h1 = hs64[c * 64 + 2 * l + 1];
            ffma2(a0, w0[2*c], h0); ffma2(a0, w0[2*c+1], h1);
            ffma2(a1, w1[2*c], h0); ffma2(a1, w1[2*c+1], h1);
            ffma2(a2, w2[2*c], h0); ffma2(a2, w2[2*c+1], h1);
        }
        float s0 = hsum2(a0), s1 = hsum2(a1), s2 = hsum2(a2);
        #pragma unroll
        for (int o = 16; o > 0; o >>= 1) {
            s0 += __shfl_xor_sync(0xffffffffu, s0, o);
            s1 += __shfl_xor_sync(0xffffffffu, s1, o);
            s2 += __shfl_xor_sync(0xffffffffu, s2, o);
        }

        if (l == 0) {
            float r  = sigm(gi_r + s0 + b_r);
            float z  = sigm(gi_z + s1 + b_z);
            float n  = tanh_fast(gi_n + r * (s2 + b_n));
            float hp = h_s[p][u];
            float hn = fmaf(z, hp - n, n);   // (1-z)*n + z*hp
            __stcg((p ? hbuf1 : hbuf0) + u, hn);
            arrive_release(&ctr[s]);         // per-warp arrival (release)
            out[(size_t)t * (2 * H) + d * H + u] = hn;
            if (s == L - 1) {
                const size_t hid_off = (size_t)L * (2 * H);
                out[hid_off + d * H + u]         = hn;
                out[hid_off + 2 * H + d * H + u] = hn;
            }
        }
    }
}

// ---------------------------------------------------------------------------
// Launch
// ---------------------------------------------------------------------------
extern "C" void kernel_launch(void* const* d_in, const int* in_sizes, int n_in,
                              void* d_out, int out_size)
{
    const float* x    = (const float*)d_in[0];
    const float* fWih = (const float*)d_in[1];
    const float* fWhh = (const float*)d_in[2];
    const float* fbih = (const float*)d_in[3];
    const float* fbhh = (const float*)d_in[4];
    const float* rWih = (const float*)d_in[5];
    const float* rWhh = (const float*)d_in[6];
    const float* rbih = (const float*)d_in[7];
    const float* rbhh = (const float*)d_in[8];
    float* out = (float*)d_out;

    reset_kernel<<<8, 256>>>();

    dim3 ggrid(G3 / 64, L / 128, 2);
    gi_gemm<<<ggrid, 256>>>(x, fWih, fbih, rWih, rbih);

    gru_recur<<<2 * NCTA, 512>>>(fWhh, fbhh, rWhh, rbhh, out);
}

// round 4
// speedup vs baseline: 1.8389x; 1.8389x over previous
#include <cuda_runtime.h>
#include <math.h>

#define H 1024
#define L 4096
#define G3 3072
#define NCTA 64     // CTAs per direction in recurrence
#define UNITS 16    // hidden units per CTA (16 warps, 1 unit/warp)

typedef unsigned long long u64;

// Scratch: precomputed input projections gi = Wih @ x_t + bih, per direction.
__device__ float g_Gi[2][L][G3];            // ~100.7 MB
__device__ unsigned int g_ctr[2 * L];       // per-step arrival counters
__device__ float g_h[2][2][H];              // [dir][step parity][H] h exchange

// ---------------------------------------------------------------------------
// PTX helpers
// ---------------------------------------------------------------------------
__device__ __forceinline__ void ffma2(u64& acc, u64 a, u64 b) {
    asm("fma.rn.f32x2 %0, %1, %2, %3;" : "=l"(acc) : "l"(a), "l"(b), "l"(acc));
}
__device__ __forceinline__ float hsum2(u64 v) {
    float lo, hi;
    asm("mov.b64 {%0, %1}, %2;" : "=f"(lo), "=f"(hi) : "l"(v));
    return lo + hi;
}
__device__ __forceinline__ u64 dup2(float v) {
    u64 r;
    asm("mov.b64 %0, {%1, %1};" : "=l"(r) : "f"(v));
    return r;
}
__device__ __forceinline__ void arrive_release(unsigned int* p) {
    asm volatile("red.release.gpu.global.add.u32 [%0], 1;" :: "l"(p) : "memory");
}
__device__ __forceinline__ unsigned int ld_acquire(const unsigned int* p) {
    unsigned int v;
    asm volatile("ld.acquire.gpu.global.u32 %0, [%1];" : "=r"(v) : "l"(p) : "memory");
    return v;
}

// ---------------------------------------------------------------------------
// Reset counters
// ---------------------------------------------------------------------------
__global__ void reset_kernel() {
    int i = blockIdx.x * blockDim.x + threadIdx.x;
    for (int k = i; k < 2 * L; k += gridDim.x * blockDim.x) g_ctr[k] = 0u;
}

// ---------------------------------------------------------------------------
// Phase 1: Gi[d][t][n] = sum_k x[t][k] * W[n][k] + b[n]
// SGEMM-NT with f32x2 packed FMAs (m-rows paired), B duplicated {b,b} in SMEM.
// ---------------------------------------------------------------------------
__device__ __forceinline__ int bpad(int n) { return n + (n >> 2); }

__global__ __launch_bounds__(256) void gi_gemm(
    const float* __restrict__ x,
    const float* __restrict__ Wf, const float* __restrict__ bf,
    const float* __restrict__ Wr, const float* __restrict__ br)
{
    const int d  = blockIdx.z;
    const float* __restrict__ W = d ? Wr : Wf;
    const float* __restrict__ b = d ? br : bf;
    const int m0 = blockIdx.y * 128;
    const int n0 = blockIdx.x * 64;

    __shared__ float As[16][132];          // [k][m]
    __shared__ u64   Bsd[16][80];          // [k][padded n], duplicated {b,b}

    const int tid = threadIdx.x;
    const int tx  = tid & 15;
    const int ty  = tid >> 4;

    u64 acc[4][4];
    #pragma unroll
    for (int i = 0; i < 4; ++i)
        #pragma unroll
        for (int j = 0; j < 4; ++j) acc[i][j] = 0ull;

    for (int k0 = 0; k0 < H; k0 += 16) {
        #pragma unroll
        for (int it = 0; it < 2; ++it) {
            int idx = tid + it * 256;
            int row = idx >> 2, kq = idx & 3;
            float4 v = *(const float4*)(x + (size_t)(m0 + row) * H + k0 + kq * 4);
            As[kq * 4 + 0][row] = v.x;
            As[kq * 4 + 1][row] = v.y;
            As[kq * 4 + 2][row] = v.z;
            As[kq * 4 + 3][row] = v.w;
        }
        {
            int row = tid >> 2, kq = tid & 3;
            float4 v = *(const float4*)(W + (size_t)(n0 + row) * H + k0 + kq * 4);
            int p = bpad(row);
            Bsd[kq * 4 + 0][p] = dup2(v.x);
            Bsd[kq * 4 + 1][p] = dup2(v.y);
            Bsd[kq * 4 + 2][p] = dup2(v.z);
            Bsd[kq * 4 + 3][p] = dup2(v.w);
        }
        __syncthreads();

        #pragma unroll
        for (int kk = 0; kk < 16; ++kk) {
            ulonglong2 A0 = *(const ulonglong2*)&As[kk][ty * 8];
            ulonglong2 A1 = *(const ulonglong2*)&As[kk][ty * 8 + 4];
            u64 am[4] = {A0.x, A0.y, A1.x, A1.y};
            const u64* brow = &Bsd[kk][bpad(tx * 4)];
            u64 bv[4] = {brow[0], brow[1], brow[2], brow[3]};
            #pragma unroll
            for (int i = 0; i < 4; ++i)
                #pragma unroll
                for (int j = 0; j < 4; ++j)
                    ffma2(acc[i][j], am[i], bv[j]);
        }
        __syncthreads();
    }

    float* __restrict__ C = &g_Gi[d][0][0];
    float4 bias = *(const float4*)(b + n0 + tx * 4);
    float bias_a[4] = {bias.x, bias.y, bias.z, bias.w};
    #pragma unroll
    for (int p = 0; p < 4; ++p) {
        float lo[4], hi[4];
        #pragma unroll
        for (int j = 0; j < 4; ++j) {
            asm("mov.b64 {%0, %1}, %2;" : "=f"(lo[j]), "=f"(hi[j]) : "l"(acc[p][j]));
            lo[j] += bias_a[j];
            hi[j] += bias_a[j];
        }
        int m = m0 + ty * 8 + 2 * p;
        *(float4*)(C + (size_t)m * G3 + n0 + tx * 4)       = make_float4(lo[0], lo[1], lo[2], lo[3]);
        *(float4*)(C + (size_t)(m + 1) * G3 + n0 + tx * 4) = make_float4(hi[0], hi[1], hi[2], hi[3]);
    }
}

// ---------------------------------------------------------------------------
// Phase 2: persistent register-resident GRU recurrence (R2 structure:
// one poller per CTA, CTA-aggregated release arrive, threshold = NCTA).
// ---------------------------------------------------------------------------
__device__ __forceinline__ float sigm(float v) {
    return 1.0f / (1.0f + __expf(-v));
}
__device__ __forceinline__ float tanh_fast(float v) {
    return 2.0f / (1.0f + __expf(-2.0f * v)) - 1.0f;
}

__global__ __launch_bounds__(512, 1) void gru_recur(
    const float* __restrict__ Whh_f, const float* __restrict__ bhh_f,
    const float* __restrict__ Whh_r, const float* __restrict__ bhh_r,
    float* __restrict__ out)
{
    const int bx  = blockIdx.x;
    const int d   = (bx >= NCTA) ? 1 : 0;
    const int cta = d ? bx - NCTA : bx;
    const int u0  = cta * UNITS;
    const int tid = threadIdx.x;
    const int w   = tid >> 5;
    const int l   = tid & 31;
    const int u   = u0 + w;

    const float* __restrict__ Whh = d ? Whh_r : Whh_f;
    const float* __restrict__ bhh = d ? bhh_r : bhh_f;
    const float* __restrict__ Gi  = &g_Gi[d][0][0];
    unsigned int* ctr = g_ctr + d * L;
    float* hbuf0 = &g_h[d][0][0];
    float* hbuf1 = &g_h[d][1][0];

    __shared__ float h_s[H];
    const u64* hs64 = (const u64*)h_s;

    // Register-resident weights: lane l holds floats [128c + 4l .. +3], c=0..7.
    u64 w0[16], w1[16], w2[16];
    {
        const u64* r0 = (const u64*)(Whh + (size_t)(u         ) * H + 4 * l);
        const u64* r1 = (const u64*)(Whh + (size_t)(u + H     ) * H + 4 * l);
        const u64* r2 = (const u64*)(Whh + (size_t)(u + 2 * H ) * H + 4 * l);
        #pragma unroll
        for (int c = 0; c < 8; ++c) {
            w0[2*c] = r0[c*64]; w0[2*c+1] = r0[c*64+1];
            w1[2*c] = r1[c*64]; w1[2*c+1] = r1[c*64+1];
            w2[2*c] = r2[c*64]; w2[2*c+1] = r2[c*64+1];
        }
    }
    const float b_r = bhh[u];
    const float b_z = bhh[u + H];
    const float b_n = bhh[u + 2 * H];

    for (int s = 0; s < L; ++s) {
        const int t = d ? (L - 1 - s) : s;

        // Gi prefetch (independent of the h dependency).
        float gi_r = 0.f, gi_z = 0.f, gi_n = 0.f;
        if (l == 0) {
            const float* g = Gi + (size_t)t * G3;
            gi_r = __ldg(g + u);
            gi_z = __ldg(g + u + H);
            gi_n = __ldg(g + u + 2 * H);
        }

        // Wait for previous step's h, stage into SMEM.
        if (s == 0) {
            if (tid < 256) ((float4*)h_s)[tid] = make_float4(0.f, 0.f, 0.f, 0.f);
        } else {
            if (tid == 0) {
                while (ld_acquire(&ctr[s - 1]) < (unsigned)NCTA) { }
            }
            __syncthreads();
            const float4* src = (const float4*)(((s - 1) & 1) ? hbuf1 : hbuf0);
            if (tid < 256) ((float4*)h_s)[tid] = __ldcg(src + tid);
        }
        __syncthreads();

        // Dot products: 3 rows x 1024, packed f32x2 (48 FFMA2 per lane).
        u64 a0 = 0ull, a1 = 0ull, a2 = 0ull;
        #pragma unroll
        for (int c = 0; c < 8; ++c) {
            u64 h0 = hs64[c * 64 + 2 * l];
            u64 h1 = hs64[c * 64 + 2 * l + 1];
            ffma2(a0, w0[2*c], h0); ffma2(a0, w0[2*c+1], h1);
            ffma2(a1, w1[2*c], h0); ffma2(a1, w1[2*c+1], h1);
            ffma2(a2, w2[2*c], h0); ffma2(a2, w2[2*c+1], h1);
        }
        float s0 = hsum2(a0), s1 = hsum2(a1), s2 = hsum2(a2);
        #pragma unroll
        for (int o = 16; o > 0; o >>= 1) {
            s0 += __shfl_xor_sync(0xffffffffu, s0, o);
            s1 += __shfl_xor_sync(0xffffffffu, s1, o);
            s2 += __shfl_xor_sync(0xffffffffu, s2, o);
        }

        if (l == 0) {
            float r  = sigm(gi_r + s0 + b_r);
            float z  = sigm(gi_z + s1 + b_z);
            float n  = tanh_fast(gi_n + r * (s2 + b_n));
            float hp = h_s[u];
            float hn = fmaf(z, hp - n, n);   // (1-z)*n + z*hp
            __stcg(((s & 1) ? hbuf1 : hbuf0) + u, hn);
            out[(size_t)t * (2 * H) + d * H + u] = hn;
            if (s == L - 1) {
                const size_t hid_off = (size_t)L * (2 * H);
                out[hid_off + d * H + u]         = hn;
                out[hid_off + 2 * H + d * H + u] = hn;
            }
        }

        // All warps' h stores done -> single cumulative release arrive per CTA.
        __syncthreads();
        if (tid == 0) arrive_release(&ctr[s]);
    }
}

// ---------------------------------------------------------------------------
// Launch
// ---------------------------------------------------------------------------
extern "C" void kernel_launch(void* const* d_in, const int* in_sizes, int n_in,
                              void* d_out, int out_size)
{
    const float* x    = (const float*)d_in[0];
    const float* fWih = (const float*)d_in[1];
    const float* fWhh = (const float*)d_in[2];
    const float* fbih = (const float*)d_in[3];
    const float* fbhh = (const float*)d_in[4];
    const float* rWih = (const float*)d_in[5];
    const float* rWhh = (const float*)d_in[6];
    const float* rbih = (const float*)d_in[7];
    const float* rbhh = (const float*)d_in[8];
    float* out = (float*)d_out;

    reset_kernel<<<8, 256>>>();

    dim3 ggrid(G3 / 64, L / 128, 2);
    gi_gemm<<<ggrid, 256>>>(x, fWih, fbih, rWih, rbih);

    gru_recur<<<2 * NCTA, 512>>>(fWhh, fbhh, rWhh, rbhh, out);
}